// round 1
// baseline (speedup 1.0000x reference)
#include <cuda_runtime.h>
#include <cstdint>

#define D 64
#define MAX_N 100000

// Scratch (device globals — no allocation allowed)
__device__ float g_sum[MAX_N * D];
__device__ float g_h[MAX_N * D];
__device__ float g_deg[MAX_N];

// ---------------------------------------------------------------------------
// Zero sums (and optionally deg)
// ---------------------------------------------------------------------------
__global__ void zero_kernel(int n_nodes, int zero_deg) {
    int i = blockIdx.x * blockDim.x + threadIdx.x;
    int stride = gridDim.x * blockDim.x;
    int n4 = n_nodes * (D / 4);
    float4 z = make_float4(0.f, 0.f, 0.f, 0.f);
    for (int j = i; j < n4; j += stride)
        ((float4*)g_sum)[j] = z;
    if (zero_deg) {
        for (int j = i; j < n_nodes; j += stride)
            g_deg[j] = 0.f;
    }
}

// ---------------------------------------------------------------------------
// Degree accumulation: deg[row[e]] += 1
// ---------------------------------------------------------------------------
__global__ void deg_kernel(const int* __restrict__ row, int E) {
    int e = blockIdx.x * blockDim.x + threadIdx.x;
    if (e < E) atomicAdd(&g_deg[row[e]], 1.0f);
}

// ---------------------------------------------------------------------------
// Scatter: g_sum[row[e]] += src[col[e]]  (64 floats per edge, 16 threads/edge)
// ---------------------------------------------------------------------------
__global__ void scatter_kernel(const float* __restrict__ src,
                               const int* __restrict__ row,
                               const int* __restrict__ col, int E) {
    long long idx = (long long)blockIdx.x * blockDim.x + threadIdx.x;
    int e = (int)(idx >> 4);
    if (e >= E) return;
    int j = (int)(idx & 15);
    int c = __ldg(&col[e]);
    int r = __ldg(&row[e]);
    float4 v = ((const float4*)(src + (size_t)c * D))[j];
    float* dst = g_sum + (size_t)r * D + j * 4;
    atomicAdd(dst + 0, v.x);
    atomicAdd(dst + 1, v.y);
    atomicAdd(dst + 2, v.z);
    atomicAdd(dst + 3, v.w);
}

// ---------------------------------------------------------------------------
// Linear: out[n] = concat(self[n], g_sum[n]/max(deg,1)) @ W + b, optional relu
// Block = 256 threads = 8 warps. Each warp handles 8 nodes.
// W ([128][64], 32KB) in smem; input vectors staged in smem (32KB).
// Lane computes output cols {2*lane, 2*lane+1} for all 8 nodes.
// ---------------------------------------------------------------------------
#define SMEM_LINEAR ((2 * D * D + 8 * 8 * 2 * D) * 4)

__global__ void linear_kernel(const float* __restrict__ self,
                              const float* __restrict__ W,   // [2D][D] row-major
                              const float* __restrict__ b,   // [D]
                              float* __restrict__ out,
                              int N, int relu) {
    extern __shared__ float smem[];
    float* sW = smem;                 // 2D*D = 8192 floats
    float* sIn = smem + 2 * D * D;    // 8 warps * 8 nodes * 128

    int tid = threadIdx.x;
    // Load W into shared (coalesced)
    for (int i = tid; i < 2 * D * D; i += blockDim.x)
        sW[i] = W[i];
    __syncthreads();

    int warp = tid >> 5;
    int lane = tid & 31;
    int node0 = (blockIdx.x * 8 + warp) * 8;
    if (node0 >= N) return;

    float* myIn = sIn + warp * 8 * (2 * D);

    // Stage 8 nodes' concat(self, agg) vectors into smem
#pragma unroll
    for (int nn = 0; nn < 8; nn++) {
        int node = node0 + nn;
        float s0 = 0.f, s1 = 0.f, a0 = 0.f, a1 = 0.f;
        if (node < N) {
            const float* sp = self + (size_t)node * D;
            s0 = sp[lane];
            s1 = sp[lane + 32];
            float inv = 1.0f / fmaxf(g_deg[node], 1.0f);
            const float* sm = g_sum + (size_t)node * D;
            a0 = sm[lane] * inv;
            a1 = sm[lane + 32] * inv;
        }
        float* dst = myIn + nn * (2 * D);
        dst[lane] = s0;
        dst[lane + 32] = s1;
        dst[64 + lane] = a0;
        dst[96 + lane] = a1;
    }
    __syncwarp();

    float acc0[8], acc1[8];
#pragma unroll
    for (int nn = 0; nn < 8; nn++) { acc0[nn] = 0.f; acc1[nn] = 0.f; }

    // Main loop over k (unrolled by 2)
#pragma unroll 4
    for (int k = 0; k < 2 * D; k += 2) {
        float2 w0 = *(const float2*)&sW[k * D + 2 * lane];
        float2 w1 = *(const float2*)&sW[(k + 1) * D + 2 * lane];
#pragma unroll
        for (int nn = 0; nn < 8; nn++) {
            float2 iv = *(const float2*)&myIn[nn * (2 * D) + k];
            acc0[nn] += iv.x * w0.x;
            acc0[nn] += iv.y * w1.x;
            acc1[nn] += iv.x * w0.y;
            acc1[nn] += iv.y * w1.y;
        }
    }

    float2 bb = *(const float2*)&b[2 * lane];
#pragma unroll
    for (int nn = 0; nn < 8; nn++) {
        int node = node0 + nn;
        if (node >= N) break;
        float r0 = acc0[nn] + bb.x;
        float r1 = acc1[nn] + bb.y;
        if (relu) { r0 = fmaxf(r0, 0.f); r1 = fmaxf(r1, 0.f); }
        *(float2*)&out[(size_t)node * D + 2 * lane] = make_float2(r0, r1);
    }
}

// ---------------------------------------------------------------------------
extern "C" void kernel_launch(void* const* d_in, const int* in_sizes, int n_in,
                              void* d_out, int out_size) {
    const float* x  = (const float*)d_in[0];
    const int*   ei = (const int*)d_in[1];
    const float* W1 = (const float*)d_in[2];
    const float* b1 = (const float*)d_in[3];
    const float* W2 = (const float*)d_in[4];
    const float* b2 = (const float*)d_in[5];
    int N = in_sizes[0] / D;
    int E = in_sizes[1] / 2;
    const int* row = ei;
    const int* col = ei + E;
    float* out = (float*)d_out;

    float* h_ptr = nullptr;
    cudaGetSymbolAddress((void**)&h_ptr, g_h);

    cudaFuncSetAttribute(linear_kernel,
                         cudaFuncAttributeMaxDynamicSharedMemorySize, SMEM_LINEAR);

    int lin_blocks = (N + 63) / 64;
    long long sc_threads = (long long)E * 16;
    int sc_blocks = (int)((sc_threads + 255) / 256);

    // Layer 1
    zero_kernel<<<512, 256>>>(N, 1);
    deg_kernel<<<(E + 255) / 256, 256>>>(row, E);
    scatter_kernel<<<sc_blocks, 256>>>(x, row, col, E);
    linear_kernel<<<lin_blocks, 256, SMEM_LINEAR>>>(x, W1, b1, h_ptr, N, 1);

    // Layer 2
    zero_kernel<<<512, 256>>>(N, 0);
    scatter_kernel<<<sc_blocks, 256>>>(h_ptr, row, col, E);
    linear_kernel<<<lin_blocks, 256, SMEM_LINEAR>>>(h_ptr, W2, b2, out, N, 0);
}

// round 2
// speedup vs baseline: 2.3821x; 2.3821x over previous
#include <cuda_runtime.h>
#include <cstdint>

#define D 64
#define MAX_N 100000
#define MAX_E 1200000
#define SCAN_BLK 1024

// Scratch (device globals — no allocation allowed)
__device__ float g_agg[MAX_N * D];     // averaged neighbor features
__device__ float g_h[MAX_N * D];       // hidden layer output
__device__ int   g_cnt[MAX_N];         // degree / histogram
__device__ int   g_off[MAX_N + 1];     // CSR offsets
__device__ int   g_cur[MAX_N];         // fill cursors
__device__ int   g_part[128];          // scan partials
__device__ int   g_ccol[MAX_E];        // CSR column indices

// ---------------------------------------------------------------------------
__global__ void zero_cnt_kernel(int n) {
    int i = blockIdx.x * blockDim.x + threadIdx.x;
    if (i < n) g_cnt[i] = 0;
}

__global__ void hist_kernel(const int* __restrict__ row, int E) {
    int e = blockIdx.x * blockDim.x + threadIdx.x;
    if (e < E) atomicAdd(&g_cnt[row[e]], 1);
}

// Block-wise exclusive scan of g_cnt -> g_off, block totals -> g_part
__global__ void scan1_kernel(int n) {
    __shared__ int s[SCAN_BLK];
    int tid = threadIdx.x;
    int i = blockIdx.x * SCAN_BLK + tid;
    int v = (i < n) ? g_cnt[i] : 0;
    s[tid] = v;
    __syncthreads();
    for (int off = 1; off < SCAN_BLK; off <<= 1) {
        int t = (tid >= off) ? s[tid - off] : 0;
        __syncthreads();
        s[tid] += t;
        __syncthreads();
    }
    if (i < n) g_off[i] = s[tid] - v;   // exclusive within block
    if (tid == SCAN_BLK - 1) g_part[blockIdx.x] = s[tid];
}

// Exclusive scan of partials (single block, 128 threads)
__global__ void scan2_kernel(int nb) {
    __shared__ int s[128];
    int tid = threadIdx.x;
    int v = (tid < nb) ? g_part[tid] : 0;
    s[tid] = v;
    __syncthreads();
    for (int off = 1; off < 128; off <<= 1) {
        int t = (tid >= off) ? s[tid - off] : 0;
        __syncthreads();
        s[tid] += t;
        __syncthreads();
    }
    if (tid < nb) g_part[tid] = s[tid] - v;
}

// Add block base, init cursors, set sentinel
__global__ void scan3_kernel(int n, int E) {
    int i = blockIdx.x * SCAN_BLK + threadIdx.x;
    if (i < n) {
        int v = g_off[i] + g_part[blockIdx.x];
        g_off[i] = v;
        g_cur[i] = v;
    }
    if (i == 0) g_off[n] = E;
}

__global__ void fill_kernel(const int* __restrict__ row,
                            const int* __restrict__ col, int E) {
    int e = blockIdx.x * blockDim.x + threadIdx.x;
    if (e < E) {
        int pos = atomicAdd(&g_cur[row[e]], 1);
        g_ccol[pos] = col[e];
    }
}

// ---------------------------------------------------------------------------
// Aggregate: one warp per node. agg[n] = mean over neighbors of src[col].
// Lane holds float2 (2 consecutive cols). Gather is L2-resident.
// ---------------------------------------------------------------------------
__global__ void aggregate_kernel(const float* __restrict__ src,
                                 float* __restrict__ agg, int N) {
    int gw = (blockIdx.x * blockDim.x + threadIdx.x) >> 5;
    if (gw >= N) return;
    int lane = threadIdx.x & 31;
    int node = gw;

    int beg = g_off[node];
    int end = g_off[node + 1];
    float ax = 0.f, ay = 0.f;
#pragma unroll 4
    for (int i = beg; i < end; i++) {
        int c = __ldg(&g_ccol[i]);
        float2 v = ((const float2*)(src + (size_t)c * D))[lane];
        ax += v.x;
        ay += v.y;
    }
    float inv = 1.0f / fmaxf((float)(end - beg), 1.0f);
    ((float2*)(agg + (size_t)node * D))[lane] = make_float2(ax * inv, ay * inv);
}

// ---------------------------------------------------------------------------
// Linear: out[n] = concat(self[n], agg[n]) @ W + b, optional relu.
// Persistent grid-stride: W loaded into smem ONCE per block.
// Block = 256 threads = 8 warps, each warp handles 8 nodes per group.
// ---------------------------------------------------------------------------
#define SMEM_LINEAR ((2 * D * D + 8 * 8 * 2 * D) * 4)

__global__ void linear_kernel(const float* __restrict__ self,
                              const float* __restrict__ agg,
                              const float* __restrict__ W,   // [2D][D] row-major
                              const float* __restrict__ b,   // [D]
                              float* __restrict__ out,
                              int N, int relu) {
    extern __shared__ float smem[];
    float* sW = smem;                 // 2D*D = 8192 floats
    float* sIn = smem + 2 * D * D;    // 8 warps * 8 nodes * 128

    int tid = threadIdx.x;
    for (int i = tid; i < 2 * D * D; i += blockDim.x)
        sW[i] = W[i];
    __syncthreads();

    int warp = tid >> 5;
    int lane = tid & 31;
    float* myIn = sIn + warp * 8 * (2 * D);
    float2 bb = *(const float2*)&b[2 * lane];

    int groups = (N + 63) / 64;
    for (int g = blockIdx.x; g < groups; g += gridDim.x) {
        int node0 = (g * 8 + warp) * 8;
        if (node0 >= N) { __syncwarp(); continue; }

        // Stage 8 nodes' concat(self, agg) vectors into smem
#pragma unroll
        for (int nn = 0; nn < 8; nn++) {
            int node = node0 + nn;
            float s0 = 0.f, s1 = 0.f, a0 = 0.f, a1 = 0.f;
            if (node < N) {
                const float* sp = self + (size_t)node * D;
                s0 = sp[lane];
                s1 = sp[lane + 32];
                const float* ap = agg + (size_t)node * D;
                a0 = ap[lane];
                a1 = ap[lane + 32];
            }
            float* dst = myIn + nn * (2 * D);
            dst[lane] = s0;
            dst[lane + 32] = s1;
            dst[64 + lane] = a0;
            dst[96 + lane] = a1;
        }
        __syncwarp();

        float acc0[8], acc1[8];
#pragma unroll
        for (int nn = 0; nn < 8; nn++) { acc0[nn] = 0.f; acc1[nn] = 0.f; }

#pragma unroll 4
        for (int k = 0; k < 2 * D; k += 2) {
            float2 w0 = *(const float2*)&sW[k * D + 2 * lane];
            float2 w1 = *(const float2*)&sW[(k + 1) * D + 2 * lane];
#pragma unroll
            for (int nn = 0; nn < 8; nn++) {
                float2 iv = *(const float2*)&myIn[nn * (2 * D) + k];
                acc0[nn] += iv.x * w0.x;
                acc0[nn] += iv.y * w1.x;
                acc1[nn] += iv.x * w0.y;
                acc1[nn] += iv.y * w1.y;
            }
        }

#pragma unroll
        for (int nn = 0; nn < 8; nn++) {
            int node = node0 + nn;
            if (node >= N) break;
            float r0 = acc0[nn] + bb.x;
            float r1 = acc1[nn] + bb.y;
            if (relu) { r0 = fmaxf(r0, 0.f); r1 = fmaxf(r1, 0.f); }
            *(float2*)&out[(size_t)node * D + 2 * lane] = make_float2(r0, r1);
        }
        __syncwarp();
    }
}

// ---------------------------------------------------------------------------
extern "C" void kernel_launch(void* const* d_in, const int* in_sizes, int n_in,
                              void* d_out, int out_size) {
    const float* x  = (const float*)d_in[0];
    const int*   ei = (const int*)d_in[1];
    const float* W1 = (const float*)d_in[2];
    const float* b1 = (const float*)d_in[3];
    const float* W2 = (const float*)d_in[4];
    const float* b2 = (const float*)d_in[5];
    int N = in_sizes[0] / D;
    int E = in_sizes[1] / 2;
    const int* row = ei;
    const int* col = ei + E;
    float* out = (float*)d_out;

    float *h_ptr = nullptr, *agg_ptr = nullptr;
    cudaGetSymbolAddress((void**)&h_ptr, g_h);
    cudaGetSymbolAddress((void**)&agg_ptr, g_agg);

    cudaFuncSetAttribute(linear_kernel,
                         cudaFuncAttributeMaxDynamicSharedMemorySize, SMEM_LINEAR);

    int scan_blocks = (N + SCAN_BLK - 1) / SCAN_BLK;
    int eb = (E + 255) / 256;
    int agg_blocks = (N * 32 + 255) / 256;
    int lin_blocks = 148 * 3;

    // --- Build CSR (reused by both layers) ---
    zero_cnt_kernel<<<(N + 255) / 256, 256>>>(N);
    hist_kernel<<<eb, 256>>>(row, E);
    scan1_kernel<<<scan_blocks, SCAN_BLK>>>(N);
    scan2_kernel<<<1, 128>>>(scan_blocks);
    scan3_kernel<<<scan_blocks, SCAN_BLK>>>(N, E);
    fill_kernel<<<eb, 256>>>(row, col, E);

    // --- Layer 1 ---
    aggregate_kernel<<<agg_blocks, 256>>>(x, agg_ptr, N);
    linear_kernel<<<lin_blocks, 256, SMEM_LINEAR>>>(x, agg_ptr, W1, b1, h_ptr, N, 1);

    // --- Layer 2 ---
    aggregate_kernel<<<agg_blocks, 256>>>(h_ptr, agg_ptr, N);
    linear_kernel<<<lin_blocks, 256, SMEM_LINEAR>>>(h_ptr, agg_ptr, W2, b2, out, N, 0);
}

// round 4
// speedup vs baseline: 2.9189x; 1.2253x over previous
#include <cuda_runtime.h>
#include <cuda_bf16.h>
#include <cstdint>

#define D 64
#define MAX_N 100000
#define MAX_E 1200000
#define SCAN_BLK 1024

// ---------------------------------------------------------------------------
// Scratch (device globals — no allocation allowed)
// ---------------------------------------------------------------------------
__device__ float g_agg[MAX_N * D];     // averaged neighbor features
__device__ float g_h[MAX_N * D];       // hidden layer output
__device__ int   g_cnt[MAX_N];         // degree / histogram
__device__ int   g_off[MAX_N + 1];     // CSR offsets
__device__ int   g_cur[MAX_N];         // fill cursors
__device__ int   g_part[128];          // scan partials
__device__ int   g_ccol[MAX_E];        // CSR column indices
__device__ __nv_bfloat16 g_Wh[2][64 * 128];  // [layer][n*128+k]  W^T hi
__device__ __nv_bfloat16 g_Wl[2][64 * 128];  // [layer][n*128+k]  W^T lo

// ---------------------------------------------------------------------------
// PTX helpers — BASE ISA ONLY (harness compiles at .target sm_103, no 'a')
// ---------------------------------------------------------------------------
__device__ __forceinline__ uint32_t smem_u32(const void* p) {
    uint32_t a;
    asm("{ .reg .u64 t; cvta.to.shared.u64 t, %1; cvt.u32.u64 %0, t; }"
        : "=r"(a) : "l"(p));
    return a;
}
__device__ __forceinline__ void ldsm_x4(uint32_t& r0, uint32_t& r1,
                                        uint32_t& r2, uint32_t& r3,
                                        uint32_t addr) {
    asm volatile("ldmatrix.sync.aligned.m8n8.x4.shared.b16 {%0,%1,%2,%3}, [%4];"
                 : "=r"(r0), "=r"(r1), "=r"(r2), "=r"(r3) : "r"(addr));
}
__device__ __forceinline__ void mma_bf16(float* c, const uint32_t* a,
                                         uint32_t b0, uint32_t b1) {
    asm volatile(
        "mma.sync.aligned.m16n8k16.row.col.f32.bf16.bf16.f32 "
        "{%0,%1,%2,%3}, {%4,%5,%6,%7}, {%8,%9}, {%0,%1,%2,%3};"
        : "+f"(c[0]), "+f"(c[1]), "+f"(c[2]), "+f"(c[3])
        : "r"(a[0]), "r"(a[1]), "r"(a[2]), "r"(a[3]), "r"(b0), "r"(b1));
}

// ---------------------------------------------------------------------------
// CSR build
// ---------------------------------------------------------------------------
__global__ void zero_cnt_kernel(int n) {
    int i = blockIdx.x * blockDim.x + threadIdx.x;
    if (i < n) g_cnt[i] = 0;
}
__global__ void hist_kernel(const int* __restrict__ row, int E) {
    int e = blockIdx.x * blockDim.x + threadIdx.x;
    if (e < E) atomicAdd(&g_cnt[row[e]], 1);
}
__global__ void scan1_kernel(int n) {
    __shared__ int s[SCAN_BLK];
    int tid = threadIdx.x;
    int i = blockIdx.x * SCAN_BLK + tid;
    int v = (i < n) ? g_cnt[i] : 0;
    s[tid] = v;
    __syncthreads();
    for (int off = 1; off < SCAN_BLK; off <<= 1) {
        int t = (tid >= off) ? s[tid - off] : 0;
        __syncthreads();
        s[tid] += t;
        __syncthreads();
    }
    if (i < n) g_off[i] = s[tid] - v;
    if (tid == SCAN_BLK - 1) g_part[blockIdx.x] = s[tid];
}
__global__ void scan2_kernel(int nb) {
    __shared__ int s[128];
    int tid = threadIdx.x;
    int v = (tid < nb) ? g_part[tid] : 0;
    s[tid] = v;
    __syncthreads();
    for (int off = 1; off < 128; off <<= 1) {
        int t = (tid >= off) ? s[tid - off] : 0;
        __syncthreads();
        s[tid] += t;
        __syncthreads();
    }
    if (tid < nb) g_part[tid] = s[tid] - v;
}
__global__ void scan3_kernel(int n, int E) {
    int i = blockIdx.x * SCAN_BLK + threadIdx.x;
    if (i < n) {
        int v = g_off[i] + g_part[blockIdx.x];
        g_off[i] = v;
        g_cur[i] = v;
    }
    if (i == 0) g_off[n] = E;
}
__global__ void fill_kernel(const int* __restrict__ row,
                            const int* __restrict__ col, int E) {
    int e = blockIdx.x * blockDim.x + threadIdx.x;
    if (e < E) {
        int pos = atomicAdd(&g_cur[row[e]], 1);
        g_ccol[pos] = col[e];
    }
}

// ---------------------------------------------------------------------------
// Aggregate: one warp per node; lane holds float2.
// ---------------------------------------------------------------------------
__global__ void aggregate_kernel(const float* __restrict__ src,
                                 float* __restrict__ agg, int N) {
    int gw = (blockIdx.x * blockDim.x + threadIdx.x) >> 5;
    if (gw >= N) return;
    int lane = threadIdx.x & 31;
    int beg = g_off[gw];
    int end = g_off[gw + 1];
    float ax = 0.f, ay = 0.f;
#pragma unroll 4
    for (int i = beg; i < end; i++) {
        int c = __ldg(&g_ccol[i]);
        float2 v = ((const float2*)(src + (size_t)c * D))[lane];
        ax += v.x;
        ay += v.y;
    }
    float inv = 1.0f / fmaxf((float)(end - beg), 1.0f);
    ((float2*)(agg + (size_t)gw * D))[lane] = make_float2(ax * inv, ay * inv);
}

// ---------------------------------------------------------------------------
// Weight prep: split W[k][n] fp32 -> Wh/Wl bf16, transposed to [n][k] K-major
// ---------------------------------------------------------------------------
__global__ void prep_w_kernel(const float* __restrict__ W1,
                              const float* __restrict__ W2) {
    int i = blockIdx.x * blockDim.x + threadIdx.x;
    if (i >= 2 * 8192) return;
    int layer = i >> 13;
    int j = i & 8191;           // j = k*64 + n
    int k = j >> 6;
    int n = j & 63;
    float w = (layer ? W2 : W1)[j];
    __nv_bfloat16 h = __float2bfloat16(w);
    float lo = w - __bfloat162float(h);
    g_Wh[layer][n * 128 + k] = h;
    g_Wl[layer][n * 128 + k] = __float2bfloat16(lo);
}

// ---------------------------------------------------------------------------
// GEMM via mma.sync (HMMA): out[128-node tile][64] =
//   concat(self, agg)[128][128] @ W + b,  bf16 3-pass split, fp32 accum.
// smem rows padded to 136 bf16 (272B) -> conflict-free ldmatrix.
// ---------------------------------------------------------------------------
#define APAD 136
#define SM_A_ELEMS (128 * APAD)
#define SM_W_ELEMS (64 * APAD)
#define SM_GEMM (256 + 2 * SM_A_ELEMS * 2 + 2 * SM_W_ELEMS * 2)

__global__ void __launch_bounds__(256, 1)
gemm_kernel(const float* __restrict__ self, const float* __restrict__ agg,
            const float* __restrict__ bias, float* __restrict__ out,
            int N, int relu, int layer) {
    extern __shared__ char smem[];
    float* bs = (float*)smem;
    __nv_bfloat16* Ah = (__nv_bfloat16*)(smem + 256);
    __nv_bfloat16* Al = Ah + SM_A_ELEMS;
    __nv_bfloat16* Wh = Al + SM_A_ELEMS;
    __nv_bfloat16* Wl = Wh + SM_W_ELEMS;

    int tid = threadIdx.x;
    int lane = tid & 31;
    int wid = tid >> 5;
    int node0 = blockIdx.x * 128;

    if (tid < 64) bs[tid] = bias[tid];

    // --- Stage W (pre-split bf16, [n][k]) into padded smem ---
    const __nv_bfloat16* gWh = g_Wh[layer];
    const __nv_bfloat16* gWl = g_Wl[layer];
#pragma unroll
    for (int it = 0; it < 8; it++) {
        int g = it * 256 + tid;            // 2048 granules of 4 bf16
        int n = g >> 5;
        int k = (g & 31) * 4;
        uint2 hv = *(const uint2*)(gWh + n * 128 + k);
        uint2 lv = *(const uint2*)(gWl + n * 128 + k);
        *(uint2*)(Wh + n * APAD + k) = hv;
        *(uint2*)(Wl + n * APAD + k) = lv;
    }

    // --- Stage A: rows=nodes(128), k: [self(0..63) | agg(64..127)], split ---
#pragma unroll
    for (int it = 0; it < 16; it++) {
        int g = it * 256 + tid;            // 4096 float4 granules
        int row = g >> 5;
        int seg = g & 31;
        int k = seg * 4;
        int node = node0 + row;
        float4 v = make_float4(0.f, 0.f, 0.f, 0.f);
        if (node < N) {
            v = (k < 64) ? ((const float4*)(self + (size_t)node * D))[seg]
                         : ((const float4*)(agg + (size_t)node * D))[seg - 16];
        }
        __nv_bfloat16 h0 = __float2bfloat16(v.x);
        __nv_bfloat16 h1 = __float2bfloat16(v.y);
        __nv_bfloat16 h2 = __float2bfloat16(v.z);
        __nv_bfloat16 h3 = __float2bfloat16(v.w);
        __nv_bfloat162 hp0(h0, h1), hp1(h2, h3);
        __nv_bfloat162 lp0(__float2bfloat16(v.x - __bfloat162float(h0)),
                           __float2bfloat16(v.y - __bfloat162float(h1)));
        __nv_bfloat162 lp1(__float2bfloat16(v.z - __bfloat162float(h2)),
                           __float2bfloat16(v.w - __bfloat162float(h3)));
        uint32_t uh0 = *(uint32_t*)&hp0, uh1 = *(uint32_t*)&hp1;
        uint32_t ul0 = *(uint32_t*)&lp0, ul1 = *(uint32_t*)&lp1;
        *(uint2*)(Ah + row * APAD + k) = make_uint2(uh0, uh1);
        *(uint2*)(Al + row * APAD + k) = make_uint2(ul0, ul1);
    }
    __syncthreads();

    // --- MMA: warp w -> rows [16w, 16w+16), all 64 cols ---
    int r0 = 16 * wid;
    float c[8][4];
#pragma unroll
    for (int a = 0; a < 8; a++)
#pragma unroll
        for (int j = 0; j < 4; j++) c[a][j] = 0.f;

    // per-lane ldmatrix base addresses
    uint32_t aBaseH = smem_u32(Ah);
    uint32_t aBaseL = smem_u32(Al);
    uint32_t wBaseH = smem_u32(Wh);
    uint32_t wBaseL = smem_u32(Wl);
    // A: row = r0 + (lane&15), kblk = 8*(lane>>4)
    uint32_t aRowOff = (uint32_t)((r0 + (lane & 15)) * APAD + 8 * (lane >> 4)) * 2;
    // B: nrow = (lane&7) + 8*((lane>>4)&1), kblk = 8*((lane>>3)&1)
    uint32_t wRowOff = (uint32_t)(((lane & 7) + 8 * ((lane >> 4) & 1)) * APAD +
                                  8 * ((lane >> 3) & 1)) * 2;

#pragma unroll
    for (int kk = 0; kk < 8; kk++) {
        uint32_t kOff = (uint32_t)(16 * kk) * 2;
        uint32_t ah[4], al[4];
        ldsm_x4(ah[0], ah[1], ah[2], ah[3], aBaseH + aRowOff + kOff);
        ldsm_x4(al[0], al[1], al[2], al[3], aBaseL + aRowOff + kOff);
#pragma unroll
        for (int g = 0; g < 4; g++) {
            uint32_t nOff = (uint32_t)(16 * g * APAD) * 2;
            uint32_t bh0, bh1, bh2, bh3, bl0, bl1, bl2, bl3;
            ldsm_x4(bh0, bh1, bh2, bh3, wBaseH + wRowOff + nOff + kOff);
            ldsm_x4(bl0, bl1, bl2, bl3, wBaseL + wRowOff + nOff + kOff);
            mma_bf16(c[2 * g],     ah, bh0, bh1);
            mma_bf16(c[2 * g],     al, bh0, bh1);
            mma_bf16(c[2 * g],     ah, bl0, bl1);
            mma_bf16(c[2 * g + 1], ah, bh2, bh3);
            mma_bf16(c[2 * g + 1], al, bh2, bh3);
            mma_bf16(c[2 * g + 1], ah, bl2, bl3);
        }
    }

    // --- Epilogue: bias + relu, direct STG ---
    int rowa = r0 + (lane >> 2);
    int nodea = node0 + rowa;
    int nodeb = nodea + 8;
    int t2 = 2 * (lane & 3);
#pragma unroll
    for (int a = 0; a < 8; a++) {
        int col = 8 * a + t2;
        float2 bb = *(float2*)&bs[col];
        if (nodea < N) {
            float ox = c[a][0] + bb.x;
            float oy = c[a][1] + bb.y;
            if (relu) { ox = fmaxf(ox, 0.f); oy = fmaxf(oy, 0.f); }
            *(float2*)(out + (size_t)nodea * D + col) = make_float2(ox, oy);
        }
        if (nodeb < N) {
            float ox = c[a][2] + bb.x;
            float oy = c[a][3] + bb.y;
            if (relu) { ox = fmaxf(ox, 0.f); oy = fmaxf(oy, 0.f); }
            *(float2*)(out + (size_t)nodeb * D + col) = make_float2(ox, oy);
        }
    }
}

// ---------------------------------------------------------------------------
extern "C" void kernel_launch(void* const* d_in, const int* in_sizes, int n_in,
                              void* d_out, int out_size) {
    const float* x  = (const float*)d_in[0];
    const int*   ei = (const int*)d_in[1];
    const float* W1 = (const float*)d_in[2];
    const float* b1 = (const float*)d_in[3];
    const float* W2 = (const float*)d_in[4];
    const float* b2 = (const float*)d_in[5];
    int N = in_sizes[0] / D;
    int E = in_sizes[1] / 2;
    const int* row = ei;
    const int* col = ei + E;
    float* out = (float*)d_out;

    float *h_ptr = nullptr, *agg_ptr = nullptr;
    cudaGetSymbolAddress((void**)&h_ptr, g_h);
    cudaGetSymbolAddress((void**)&agg_ptr, g_agg);

    cudaFuncSetAttribute(gemm_kernel,
                         cudaFuncAttributeMaxDynamicSharedMemorySize, SM_GEMM);

    int scan_blocks = (N + SCAN_BLK - 1) / SCAN_BLK;
    int eb = (E + 255) / 256;
    int agg_blocks = (N * 32 + 255) / 256;
    int tiles = (N + 127) / 128;

    // --- Build CSR (reused by both layers) + weight prep ---
    prep_w_kernel<<<(2 * 8192 + 255) / 256, 256>>>(W1, W2);
    zero_cnt_kernel<<<(N + 255) / 256, 256>>>(N);
    hist_kernel<<<eb, 256>>>(row, E);
    scan1_kernel<<<scan_blocks, SCAN_BLK>>>(N);
    scan2_kernel<<<1, 128>>>(scan_blocks);
    scan3_kernel<<<scan_blocks, SCAN_BLK>>>(N, E);
    fill_kernel<<<eb, 256>>>(row, col, E);

    // --- Layer 1 ---
    aggregate_kernel<<<agg_blocks, 256>>>(x, agg_ptr, N);
    gemm_kernel<<<tiles, 256, SM_GEMM>>>(x, agg_ptr, b1, h_ptr, N, 1, 0);

    // --- Layer 2 ---
    aggregate_kernel<<<agg_blocks, 256>>>(h_ptr, agg_ptr, N);
    gemm_kernel<<<tiles, 256, SM_GEMM>>>(h_ptr, agg_ptr, b2, out, N, 0, 1);
}